// round 15
// baseline (speedup 1.0000x reference)
#include <cuda_runtime.h>
#include <cuda_bf16.h>
#include <math.h>

#define B_    8
#define LQ_   2048
#define LK_   1024
#define QIN   1124
#define KIN   10100
#define PROJ_ 500
#define HEADS 10
#define HD    50

#define KPQ   1152   // QIN padded to mult of 32
#define KPK   10112  // KIN padded to mult of 32
#define NP    512    // PROJ padded
#define HDP   64     // head_dim padded for MMA

typedef unsigned int u32;

// ---------------- scratch (allocation-free; zero-initialized) ----------------
__device__ float g_attn[B_ * LQ_ * HEADS];

__device__ __nv_bfloat16 g_wqh[KPQ * NP];        // W [Kp][NP] row-major, hi/lo
__device__ __nv_bfloat16 g_wql[KPQ * NP];
__device__ __nv_bfloat16 g_wkh[KPK * NP];
__device__ __nv_bfloat16 g_wkl[KPK * NP];

// projected q/k in attention layout [b, head, seq, HDP], bf16 hi/lo
// pad columns [50,64) never written -> stay zero (device globals zero-init)
__device__ __nv_bfloat16 g_qah[B_ * HEADS * LQ_ * HDP];
__device__ __nv_bfloat16 g_qal[B_ * HEADS * LQ_ * HDP];
__device__ __nv_bfloat16 g_kah[B_ * HEADS * LK_ * HDP];
__device__ __nv_bfloat16 g_kal[B_ * HEADS * LK_ * HDP];

// ------- fp32 -> (hi,lo) bf16 split for the WEIGHTS only (small) ------------
__device__ __forceinline__ u32 pack_bf2(__nv_bfloat16 lo, __nv_bfloat16 hi) {
    return (u32)__bfloat16_as_ushort(lo) | ((u32)__bfloat16_as_ushort(hi) << 16);
}
__global__ void split_bf16_v(const float* __restrict__ X,
                             __nv_bfloat16* __restrict__ H,
                             __nv_bfloat16* __restrict__ L,
                             int rows, int cols, int colsp)
{
    int r = blockIdx.x;
    bool rv = (r < rows);
    const float* Xr = X + (size_t)r * cols;
    for (int c8 = threadIdx.x * 8; c8 < colsp; c8 += blockDim.x * 8) {
        float x[8];
        if (rv && c8 + 8 <= cols) {
            float4 a = *(const float4*)(Xr + c8);
            float4 b = *(const float4*)(Xr + c8 + 4);
            x[0] = a.x; x[1] = a.y; x[2] = a.z; x[3] = a.w;
            x[4] = b.x; x[5] = b.y; x[6] = b.z; x[7] = b.w;
        } else {
#pragma unroll
            for (int i = 0; i < 8; i++) {
                int c = c8 + i;
                x[i] = (rv && c < cols) ? Xr[c] : 0.0f;
            }
        }
        __nv_bfloat16 hb[8], lb[8];
#pragma unroll
        for (int i = 0; i < 8; i++) {
            hb[i] = __float2bfloat16(x[i]);
            lb[i] = __float2bfloat16(x[i] - __bfloat162float(hb[i]));
        }
        size_t o = (size_t)r * colsp + c8;
        uint4 hv, lv;
        hv.x = pack_bf2(hb[0], hb[1]); hv.y = pack_bf2(hb[2], hb[3]);
        hv.z = pack_bf2(hb[4], hb[5]); hv.w = pack_bf2(hb[6], hb[7]);
        lv.x = pack_bf2(lb[0], lb[1]); lv.y = pack_bf2(lb[2], lb[3]);
        lv.z = pack_bf2(lb[4], lb[5]); lv.w = pack_bf2(lb[6], lb[7]);
        *(uint4*)(H + o) = hv;
        *(uint4*)(L + o) = lv;
    }
}

// ---------------- mma / ldmatrix / cp.async helpers ----------------
__device__ __forceinline__ void ldsm_x4(u32* r, u32 addr) {
    asm volatile("ldmatrix.sync.aligned.m8n8.x4.shared.b16 {%0,%1,%2,%3}, [%4];"
        : "=r"(r[0]), "=r"(r[1]), "=r"(r[2]), "=r"(r[3]) : "r"(addr));
}
__device__ __forceinline__ void ldsm_x4_t(u32* r, u32 addr) {
    asm volatile("ldmatrix.sync.aligned.m8n8.x4.trans.shared.b16 {%0,%1,%2,%3}, [%4];"
        : "=r"(r[0]), "=r"(r[1]), "=r"(r[2]), "=r"(r[3]) : "r"(addr));
}
__device__ __forceinline__ void mma_bf16(float* d, const u32* a, const u32* b) {
    asm volatile(
        "mma.sync.aligned.m16n8k16.row.col.f32.bf16.bf16.f32 "
        "{%0,%1,%2,%3},{%4,%5,%6,%7},{%8,%9},{%0,%1,%2,%3};"
        : "+f"(d[0]), "+f"(d[1]), "+f"(d[2]), "+f"(d[3])
        : "r"(a[0]), "r"(a[1]), "r"(a[2]), "r"(a[3]), "r"(b[0]), "r"(b[1]));
}
__device__ __forceinline__ void cp16(u32 dst, const void* src) {
    asm volatile("cp.async.cg.shared.global [%0], [%1], 16;"
                 :: "r"(dst), "l"(src));
}
__device__ __forceinline__ void cp_commit() {
    asm volatile("cp.async.commit_group;" ::: "memory");
}
template <int N>
__device__ __forceinline__ void cp_wait() {
    asm volatile("cp.async.wait_group %0;" :: "n"(N) : "memory");
}

// ------- bf16x3 GEMM, fused A split, ONE barrier per k-tile (R14-proven) ----
#define BM  128
#define BN  128
#define BKB 32
#define AST 40
#define WST 136
#define A_BUF (BM * AST)
#define W_BUF (BKB * WST)
#define GEMM_SMEM ((4 * A_BUF + 6 * W_BUF) * 2)   // 93184 B

__global__ __launch_bounds__(256, 2) void gemm_bf16x3_f(
    const float* __restrict__ A32,
    const __nv_bfloat16* __restrict__ Wh, const __nv_bfloat16* __restrict__ Wl,
    const float* __restrict__ bias,
    __nv_bfloat16* __restrict__ DH, __nv_bfloat16* __restrict__ DL,
    int K, int Kp, int seqshift, int bi0)
{
    extern __shared__ __nv_bfloat16 sm[];
    __nv_bfloat16* sAh = sm;
    __nv_bfloat16* sAl = sm + 2 * A_BUF;
    __nv_bfloat16* sWh = sm + 4 * A_BUF;
    __nv_bfloat16* sWl = sm + 4 * A_BUF + 3 * W_BUF;
    const u32 bAh0 = (u32)__cvta_generic_to_shared(sAh);
    const u32 bAl0 = (u32)__cvta_generic_to_shared(sAl);
    const u32 bWh0 = (u32)__cvta_generic_to_shared(sWh);
    const u32 bWl0 = (u32)__cvta_generic_to_shared(sWl);

    const int t    = threadIdx.x;
    const int lane = t & 31;
    const int warp = t >> 5;
    const int wm   = warp >> 1;
    const int wn   = warp & 1;
    const int m0   = blockIdx.y * BM;
    const int n0   = blockIdx.x * BN;

    const int ar  = t >> 1;
    const int acb = (t & 1) * 16;
    const int wr = t >> 3;
    const int wc = t & 7;

    float av[16];

    auto load_a_regs = [&](int k0) {
        const float* p = A32 + (size_t)(m0 + ar) * K + k0 + acb;
        if (k0 + BKB <= K) {
#pragma unroll
            for (int i = 0; i < 4; i++) {
                float4 v = *(const float4*)(p + i * 4);
                av[4 * i]     = v.x;
                av[4 * i + 1] = v.y;
                av[4 * i + 2] = v.z;
                av[4 * i + 3] = v.w;
            }
        } else {
#pragma unroll
            for (int i = 0; i < 16; i++) {
                int c = k0 + acb + i;
                av[i] = (c < K) ? p[i] : 0.0f;
            }
        }
    };
    auto store_a_smem = [&](int buf) {
        __nv_bfloat16 hb[16], lb[16];
#pragma unroll
        for (int i = 0; i < 16; i++) {
            hb[i] = __float2bfloat16(av[i]);
            lb[i] = __float2bfloat16(av[i] - __bfloat162float(hb[i]));
        }
        int base = buf * A_BUF + ar * AST + acb;
#pragma unroll
        for (int hf = 0; hf < 2; hf++) {
            uint4 hv, lv;
            hv.x = pack_bf2(hb[8 * hf + 0], hb[8 * hf + 1]);
            hv.y = pack_bf2(hb[8 * hf + 2], hb[8 * hf + 3]);
            hv.z = pack_bf2(hb[8 * hf + 4], hb[8 * hf + 5]);
            hv.w = pack_bf2(hb[8 * hf + 6], hb[8 * hf + 7]);
            lv.x = pack_bf2(lb[8 * hf + 0], lb[8 * hf + 1]);
            lv.y = pack_bf2(lb[8 * hf + 2], lb[8 * hf + 3]);
            lv.z = pack_bf2(lb[8 * hf + 4], lb[8 * hf + 5]);
            lv.w = pack_bf2(lb[8 * hf + 6], lb[8 * hf + 7]);
            *(uint4*)(sAh + base + 8 * hf) = hv;
            *(uint4*)(sAl + base + 8 * hf) = lv;
        }
    };
    auto load_w = [&](int buf, int k0) {
#pragma unroll
        for (int i = 0; i < 2; i++) {
            int ch = wc + i * 8;
            size_t g = (size_t)(k0 + wr) * NP + n0 + ch * 8;
            u32 s = (u32)((buf * W_BUF + wr * WST + ch * 8) * 2);
            cp16(bWh0 + s, Wh + g);
            cp16(bWl0 + s, Wl + g);
        }
        cp_commit();
    };

    float acc[2][8][4];
#pragma unroll
    for (int mt = 0; mt < 2; mt++)
#pragma unroll
        for (int nt = 0; nt < 8; nt++)
#pragma unroll
            for (int e = 0; e < 4; e++) acc[mt][nt][e] = 0.0f;

    const int lrow = lane & 15;
    const int lcol = lane >> 4;
    const int ntiles = Kp / BKB;

    load_a_regs(0);
    store_a_smem(0);
    if (ntiles > 1) load_a_regs(BKB);
    load_w(0, 0);
    if (ntiles > 1) load_w(1, BKB);

    int wcur = 0;
    for (int tl = 0; tl < ntiles; ++tl) {
        const int cur = tl & 1;
        if (tl + 1 < ntiles) cp_wait<1>(); else cp_wait<0>();
        __syncthreads();

        int wnext = wcur + 2; if (wnext >= 3) wnext -= 3;
        if (tl + 2 < ntiles) load_w(wnext, (tl + 2) * BKB);

        if (tl + 1 < ntiles) store_a_smem(cur ^ 1);
        if (tl + 2 < ntiles) load_a_regs((tl + 2) * BKB);

        const u32 aHb = bAh0 + cur * A_BUF * 2;
        const u32 aLb = bAl0 + cur * A_BUF * 2;
        const u32 wHb = bWh0 + wcur * W_BUF * 2;
        const u32 wLb = bWl0 + wcur * W_BUF * 2;

#pragma unroll
        for (int kk = 0; kk < 2; kk++) {
            u32 aH[2][4], aL[2][4];
#pragma unroll
            for (int mt = 0; mt < 2; mt++) {
                u32 off = ((wm * 32 + mt * 16 + lrow) * AST + kk * 16 + lcol * 8) * 2;
                ldsm_x4(aH[mt], aHb + off);
                ldsm_x4(aL[mt], aLb + off);
            }
#pragma unroll
            for (int np2 = 0; np2 < 2; np2++) {
                u32 bH[2][4], bL[2][4];
#pragma unroll
                for (int q = 0; q < 2; q++) {
                    int nq = np2 * 2 + q;
                    u32 off = ((kk * 16 + lrow) * WST + wn * 64 + nq * 16 + lcol * 8) * 2;
                    ldsm_x4_t(bH[q], wHb + off);
                    ldsm_x4_t(bL[q], wLb + off);
                }
#pragma unroll
                for (int mt = 0; mt < 2; mt++)
#pragma unroll
                    for (int q = 0; q < 2; q++)
#pragma unroll
                        for (int j = 0; j < 2; j++)
                            mma_bf16(acc[mt][(np2 * 2 + q) * 2 + j], aH[mt], bH[q] + 2 * j);
#pragma unroll
                for (int mt = 0; mt < 2; mt++)
#pragma unroll
                    for (int q = 0; q < 2; q++)
#pragma unroll
                        for (int j = 0; j < 2; j++)
                            mma_bf16(acc[mt][(np2 * 2 + q) * 2 + j], aH[mt], bL[q] + 2 * j);
#pragma unroll
                for (int mt = 0; mt < 2; mt++)
#pragma unroll
                    for (int q = 0; q < 2; q++)
#pragma unroll
                        for (int j = 0; j < 2; j++)
                            mma_bf16(acc[mt][(np2 * 2 + q) * 2 + j], aL[mt], bH[q] + 2 * j);
            }
        }

        if (++wcur == 3) wcur = 0;
    }

    // epilogue: write bf16 hi/lo into [b, head, seq, HDP] with batch offset bi0
    const int seqlen = 1 << seqshift;
#pragma unroll
    for (int mt = 0; mt < 2; mt++) {
#pragma unroll
        for (int nt = 0; nt < 8; nt++) {
            int row = wm * 32 + mt * 16 + (lane >> 2);
            int col = wn * 64 + nt * 8 + (lane & 3) * 2;
#pragma unroll
            for (int e = 0; e < 4; e++) {
                int m = m0 + row + ((e >> 1) ? 8 : 0);
                int n = n0 + col + (e & 1);
                if (n >= PROJ_) continue;
                int head = n / HD;
                int c    = n - head * HD;
                int bi   = (m >> seqshift) + bi0;
                int si   = m & (seqlen - 1);
                float x = acc[mt][nt][e] + bias[n];
                __nv_bfloat16 h = __float2bfloat16(x);
                size_t o = ((size_t)(bi * HEADS + head) * seqlen + si) * HDP + c;
                DH[o] = h;
                DL[o] = __float2bfloat16(x - __bfloat162float(h));
            }
        }
    }
}

// ---------------- tensor-core attention (R11-proven, + batch offset) --------
#define ATT_ST 72
#define QH_OFF 0
#define QL_OFF (128 * ATT_ST * 2)
#define KH_OFF (2 * QL_OFF)
#define KL_OFF (3 * QL_OFF)
#define V_OFF  (4 * QL_OFF)
#define ATT_SMEM (V_OFF + 128 * 4)

__global__ __launch_bounds__(256, 2) void attn_tc(const float* __restrict__ value,
                                                  int b0)
{
    extern __shared__ char smc[];
    const u32 sb = (u32)__cvta_generic_to_shared(smc);
    float* vsh = (float*)(smc + V_OFF);

    const int b  = blockIdx.z + b0;
    const int h  = blockIdx.y;
    const int q0 = blockIdx.x * 128;
    const int t  = threadIdx.x;
    const int lane = t & 31;
    const int w    = t >> 5;

    {
        const __nv_bfloat16* qh = g_qah + ((size_t)(b * HEADS + h) * LQ_ + q0) * HDP;
        const __nv_bfloat16* ql = g_qal + ((size_t)(b * HEADS + h) * LQ_ + q0) * HDP;
#pragma unroll
        for (int i = 0; i < 4; i++) {
            int idx = t + i * 256;
            int r = idx >> 3, c = idx & 7;
            uint4 vh = *(const uint4*)(qh + (size_t)r * HDP + c * 8);
            uint4 vl = *(const uint4*)(ql + (size_t)r * HDP + c * 8);
            *(uint4*)(smc + QH_OFF + (r * ATT_ST + c * 8) * 2) = vh;
            *(uint4*)(smc + QL_OFF + (r * ATT_ST + c * 8) * 2) = vl;
        }
    }

    float accA[2] = {0.f, 0.f}, accL[2] = {0.f, 0.f};
    const float scale = 0.14142135623730951f;

    const int bg  = lane >> 3;
    const int bi8 = lane & 7;
    const int brow_off = ((bg & 2) ? 8 : 0) + bi8;
    const int bcol_off = (bg & 1) ? 8 : 0;

    for (int kt = 0; kt < LK_; kt += 128) {
        __syncthreads();
        {
            const __nv_bfloat16* kh = g_kah + ((size_t)(b * HEADS + h) * LK_ + kt) * HDP;
            const __nv_bfloat16* kl = g_kal + ((size_t)(b * HEADS + h) * LK_ + kt) * HDP;
#pragma unroll
            for (int i = 0; i < 4; i++) {
                int idx = t + i * 256;
                int r = idx >> 3, c = idx & 7;
                uint4 vh = *(const uint4*)(kh + (size_t)r * HDP + c * 8);
                uint4 vl = *(const uint4*)(kl + (size_t)r * HDP + c * 8);
                *(uint4*)(smc + KH_OFF + (r * ATT_ST + c * 8) * 2) = vh;
                *(uint4*)(smc + KL_OFF + (r * ATT_ST + c * 8) * 2) = vl;
            }
            if (t < 128) vsh[t] = value[b * LK_ + kt + t];
        }
        __syncthreads();

#pragma unroll
        for (int half = 0; half < 2; half++) {
            float S[8][4];
#pragma unroll
            for (int nt = 0; nt < 8; nt++)
#pragma unroll
                for (int e = 0; e < 4; e++) S[nt][e] = 0.0f;

#pragma unroll
            for (int ks = 0; ks < 4; ks++) {
                const int k0 = ks * 16;
                u32 aH[4], aL[4];
                {
                    u32 off = ((w * 16 + (lane & 15)) * ATT_ST + k0 + (lane >> 4) * 8) * 2;
                    ldsm_x4(aH, sb + QH_OFF + off);
                    ldsm_x4(aL, sb + QL_OFF + off);
                }
                u32 bH[4][4], bL[4][4];
#pragma unroll
                for (int ng2 = 0; ng2 < 4; ng2++) {
                    const int ng = half * 4 + ng2;
                    u32 off = ((ng * 16 + brow_off) * ATT_ST + k0 + bcol_off) * 2;
                    ldsm_x4(bH[ng2], sb + KH_OFF + off);
                    ldsm_x4(bL[ng2], sb + KL_OFF + off);
                }
#pragma unroll
                for (int ng2 = 0; ng2 < 4; ng2++)
#pragma unroll
                    for (int j = 0; j < 2; j++)
                        mma_bf16(S[2 * ng2 + j], aH, bH[ng2] + 2 * j);
#pragma unroll
                for (int ng2 = 0; ng2 < 4; ng2++)
#pragma unroll
                    for (int j = 0; j < 2; j++)
                        mma_bf16(S[2 * ng2 + j], aH, bL[ng2] + 2 * j);
#pragma unroll
                for (int ng2 = 0; ng2 < 4; ng2++)
#pragma unroll
                    for (int j = 0; j < 2; j++)
                        mma_bf16(S[2 * ng2 + j], aL, bH[ng2] + 2 * j);
            }

#pragma unroll
            for (int nt = 0; nt < 8; nt++) {
                int n = (half * 8 + nt) * 8 + (lane & 3) * 2;
                float v0 = vsh[n], v1 = vsh[n + 1];
                float e0 = __expf(S[nt][0] * scale);
                float e1 = __expf(S[nt][1] * scale);
                float e2 = __expf(S[nt][2] * scale);
                float e3 = __expf(S[nt][3] * scale);
                accA[0] += e0 * v0 + e1 * v1;
                accL[0] += e0 + e1;
                accA[1] += e2 * v0 + e3 * v1;
                accL[1] += e2 + e3;
            }
        }
    }

#pragma unroll
    for (int r = 0; r < 2; r++) {
#pragma unroll
        for (int o = 1; o <= 2; o <<= 1) {
            accA[r] += __shfl_xor_sync(0xffffffffu, accA[r], o);
            accL[r] += __shfl_xor_sync(0xffffffffu, accL[r], o);
        }
    }
    if ((lane & 3) == 0) {
        int row = q0 + w * 16 + (lane >> 2);
        g_attn[((size_t)b * LQ_ + row) * HEADS + h]     = accA[0] / accL[0];
        g_attn[((size_t)b * LQ_ + row + 8) * HEADS + h] = accA[1] / accL[1];
    }
}

// ---------------- tiny MLP ----------------
__global__ __launch_bounds__(256) void mlp_kernel(
    const float* __restrict__ W1, const float* __restrict__ b1,
    const float* __restrict__ W2, const float* __restrict__ b2,
    float* __restrict__ out)
{
    int idx = blockIdx.x * blockDim.x + threadIdx.x;
    if (idx >= B_ * LQ_) return;

    float o[HEADS];
#pragma unroll
    for (int i = 0; i < HEADS; i++) o[i] = g_attn[(size_t)idx * HEADS + i];

    float y = b2[0];
#pragma unroll
    for (int j = 0; j < 10; j++) {
        float hj = b1[j];
#pragma unroll
        for (int i = 0; i < HEADS; i++) hj += o[i] * W1[i * 10 + j];
        hj = fmaxf(hj, 0.0f);
        y += hj * W2[j];
    }
    out[idx] = fmaxf(y, 0.0f);
}

// ---------------------------------------------------------------------------
extern "C" void kernel_launch(void* const* d_in, const int* in_sizes, int n_in,
                              void* d_out, int out_size)
{
    const float* query = (const float*)d_in[0];
    const float* key   = (const float*)d_in[1];
    const float* value = (const float*)d_in[2];
    const float* Wq    = (const float*)d_in[3];
    const float* bq    = (const float*)d_in[4];
    const float* Wk    = (const float*)d_in[5];
    const float* bk    = (const float*)d_in[6];
    const float* W1    = (const float*)d_in[7];
    const float* b1    = (const float*)d_in[8];
    const float* W2    = (const float*)d_in[9];
    const float* b2    = (const float*)d_in[10];
    float* out = (float*)d_out;

    static cudaStream_t sQ = nullptr, sA = nullptr;
    static cudaEvent_t evFork = nullptr, evQ = nullptr, evK0 = nullptr, evA0 = nullptr;
    if (sQ == nullptr) {
        cudaStreamCreateWithFlags(&sQ, cudaStreamNonBlocking);
        cudaStreamCreateWithFlags(&sA, cudaStreamNonBlocking);
        cudaEventCreateWithFlags(&evFork, cudaEventDisableTiming);
        cudaEventCreateWithFlags(&evQ,    cudaEventDisableTiming);
        cudaEventCreateWithFlags(&evK0,   cudaEventDisableTiming);
        cudaEventCreateWithFlags(&evA0,   cudaEventDisableTiming);
    }

    __nv_bfloat16 *wqh, *wql, *wkh, *wkl, *qah, *qal, *kah, *kal;
    cudaGetSymbolAddress((void**)&wqh, g_wqh);
    cudaGetSymbolAddress((void**)&wql, g_wql);
    cudaGetSymbolAddress((void**)&wkh, g_wkh);
    cudaGetSymbolAddress((void**)&wkl, g_wkl);
    cudaGetSymbolAddress((void**)&qah, g_qah);
    cudaGetSymbolAddress((void**)&qal, g_qal);
    cudaGetSymbolAddress((void**)&kah, g_kah);
    cudaGetSymbolAddress((void**)&kal, g_kal);

    cudaFuncSetAttribute(gemm_bf16x3_f,
                         cudaFuncAttributeMaxDynamicSharedMemorySize, GEMM_SMEM);
    cudaFuncSetAttribute(attn_tc,
                         cudaFuncAttributeMaxDynamicSharedMemorySize, ATT_SMEM);

    const int HB = B_ / 2;   // half-batch = 4

    // ---- fork ----
    cudaEventRecord(evFork, 0);
    cudaStreamWaitEvent(sQ, evFork, 0);

    // q-chain (sQ): Wq split + full q-GEMM
    split_bf16_v<<<KPQ, 64, 0, sQ>>>(Wq, wqh, wql, QIN, PROJ_, NP);
    {
        dim3 grid(NP / BN, (B_ * LQ_) / BM);
        gemm_bf16x3_f<<<grid, 256, GEMM_SMEM, sQ>>>(query, wqh, wql, bq,
                                                    qah, qal, QIN, KPQ, 11, 0);
    }
    cudaEventRecord(evQ, sQ);

    // k-chain (default): Wk split, then k-GEMM in two half-batch launches
    split_bf16_v<<<KPK, 64>>>(Wk, wkh, wkl, KIN, PROJ_, NP);
    {
        dim3 grid(NP / BN, (HB * LK_) / BM);
        gemm_bf16x3_f<<<grid, 256, GEMM_SMEM>>>(key, wkh, wkl, bk,
                                                kah, kal, KIN, KPK, 10, 0);
        cudaEventRecord(evK0, 0);
        gemm_bf16x3_f<<<grid, 256, GEMM_SMEM>>>(key + (size_t)HB * LK_ * KIN,
                                                wkh, wkl, bk,
                                                kah, kal, KIN, KPK, 10, HB);
    }

    // attention for batches 0..3 overlaps the second k-GEMM half (stream sA)
    cudaStreamWaitEvent(sA, evK0, 0);
    cudaStreamWaitEvent(sA, evQ, 0);
    {
        dim3 grid(LQ_ / 128, HEADS, HB);
        attn_tc<<<grid, 256, ATT_SMEM, sA>>>(value, 0);
    }
    cudaEventRecord(evA0, sA);

    // attention for batches 4..7 on the default stream (after k half 1)
    cudaStreamWaitEvent(0, evQ, 0);
    {
        dim3 grid(LQ_ / 128, HEADS, HB);
        attn_tc<<<grid, 256, ATT_SMEM>>>(value, HB);
    }

    // join and MLP
    cudaStreamWaitEvent(0, evA0, 0);
    {
        int n = B_ * LQ_;
        mlp_kernel<<<(n + 255) / 256, 256>>>(W1, b1, W2, b2, out);
    }
}

// round 16
// speedup vs baseline: 1.5014x; 1.5014x over previous
#include <cuda_runtime.h>
#include <cuda_bf16.h>
#include <math.h>

#define B_    8
#define LQ_   2048
#define LK_   1024
#define QIN   1124
#define KIN   10100
#define PROJ_ 500
#define HEADS 10
#define HD    50

#define KPQ   1152   // QIN padded to mult of 32
#define KPK   10112  // KIN padded to mult of 32
#define NP    512    // PROJ padded
#define HDP   64     // head_dim padded for MMA

typedef unsigned int u32;

// ---------------- scratch (allocation-free; zero-initialized) ----------------
__device__ float g_attn[B_ * LQ_ * HEADS];

__device__ __nv_bfloat16 g_wqh[KPQ * NP];        // W [Kp][NP] row-major, hi/lo
__device__ __nv_bfloat16 g_wql[KPQ * NP];
__device__ __nv_bfloat16 g_wkh[KPK * NP];
__device__ __nv_bfloat16 g_wkl[KPK * NP];

// projected q/k in attention layout [b, head, seq, HDP], bf16 hi/lo
// pad columns [50,64) never written -> stay zero (device globals zero-init)
__device__ __nv_bfloat16 g_qah[B_ * HEADS * LQ_ * HDP];
__device__ __nv_bfloat16 g_qal[B_ * HEADS * LQ_ * HDP];
__device__ __nv_bfloat16 g_kah[B_ * HEADS * LK_ * HDP];
__device__ __nv_bfloat16 g_kal[B_ * HEADS * LK_ * HDP];

// ------- fp32 -> (hi,lo) bf16 split for the WEIGHTS only (small) ------------
__device__ __forceinline__ u32 pack_bf2(__nv_bfloat16 lo, __nv_bfloat16 hi) {
    return (u32)__bfloat16_as_ushort(lo) | ((u32)__bfloat16_as_ushort(hi) << 16);
}
__global__ void split_bf16_v(const float* __restrict__ X,
                             __nv_bfloat16* __restrict__ H,
                             __nv_bfloat16* __restrict__ L,
                             int rows, int cols, int colsp)
{
    int r = blockIdx.x;
    bool rv = (r < rows);
    const float* Xr = X + (size_t)r * cols;
    for (int c8 = threadIdx.x * 8; c8 < colsp; c8 += blockDim.x * 8) {
        float x[8];
        if (rv && c8 + 8 <= cols) {
            float4 a = *(const float4*)(Xr + c8);
            float4 b = *(const float4*)(Xr + c8 + 4);
            x[0] = a.x; x[1] = a.y; x[2] = a.z; x[3] = a.w;
            x[4] = b.x; x[5] = b.y; x[6] = b.z; x[7] = b.w;
        } else {
#pragma unroll
            for (int i = 0; i < 8; i++) {
                int c = c8 + i;
                x[i] = (rv && c < cols) ? Xr[c] : 0.0f;
            }
        }
        __nv_bfloat16 hb[8], lb[8];
#pragma unroll
        for (int i = 0; i < 8; i++) {
            hb[i] = __float2bfloat16(x[i]);
            lb[i] = __float2bfloat16(x[i] - __bfloat162float(hb[i]));
        }
        size_t o = (size_t)r * colsp + c8;
        uint4 hv, lv;
        hv.x = pack_bf2(hb[0], hb[1]); hv.y = pack_bf2(hb[2], hb[3]);
        hv.z = pack_bf2(hb[4], hb[5]); hv.w = pack_bf2(hb[6], hb[7]);
        lv.x = pack_bf2(lb[0], lb[1]); lv.y = pack_bf2(lb[2], lb[3]);
        lv.z = pack_bf2(lb[4], lb[5]); lv.w = pack_bf2(lb[6], lb[7]);
        *(uint4*)(H + o) = hv;
        *(uint4*)(L + o) = lv;
    }
}

// ---------------- mma / ldmatrix / cp.async helpers ----------------
__device__ __forceinline__ void ldsm_x4(u32* r, u32 addr) {
    asm volatile("ldmatrix.sync.aligned.m8n8.x4.shared.b16 {%0,%1,%2,%3}, [%4];"
        : "=r"(r[0]), "=r"(r[1]), "=r"(r[2]), "=r"(r[3]) : "r"(addr));
}
__device__ __forceinline__ void ldsm_x4_t(u32* r, u32 addr) {
    asm volatile("ldmatrix.sync.aligned.m8n8.x4.trans.shared.b16 {%0,%1,%2,%3}, [%4];"
        : "=r"(r[0]), "=r"(r[1]), "=r"(r[2]), "=r"(r[3]) : "r"(addr));
}
__device__ __forceinline__ void mma_bf16(float* d, const u32* a, const u32* b) {
    asm volatile(
        "mma.sync.aligned.m16n8k16.row.col.f32.bf16.bf16.f32 "
        "{%0,%1,%2,%3},{%4,%5,%6,%7},{%8,%9},{%0,%1,%2,%3};"
        : "+f"(d[0]), "+f"(d[1]), "+f"(d[2]), "+f"(d[3])
        : "r"(a[0]), "r"(a[1]), "r"(a[2]), "r"(a[3]), "r"(b[0]), "r"(b[1]));
}
__device__ __forceinline__ void cp16(u32 dst, const void* src) {
    asm volatile("cp.async.cg.shared.global [%0], [%1], 16;"
                 :: "r"(dst), "l"(src));
}
__device__ __forceinline__ void cp_commit() {
    asm volatile("cp.async.commit_group;" ::: "memory");
}
template <int N>
__device__ __forceinline__ void cp_wait() {
    asm volatile("cp.async.wait_group %0;" :: "n"(N) : "memory");
}

// ------- bf16x3 GEMM, fused A split, ONE barrier per k-tile (R14-proven) ----
#define BM  128
#define BN  128
#define BKB 32
#define AST 40
#define WST 136
#define A_BUF (BM * AST)
#define W_BUF (BKB * WST)
#define GEMM_SMEM ((4 * A_BUF + 6 * W_BUF) * 2)   // 93184 B

__global__ __launch_bounds__(256, 2) void gemm_bf16x3_f(
    const float* __restrict__ A32,
    const __nv_bfloat16* __restrict__ Wh, const __nv_bfloat16* __restrict__ Wl,
    const float* __restrict__ bias,
    __nv_bfloat16* __restrict__ DH, __nv_bfloat16* __restrict__ DL,
    int K, int Kp, int seqshift)
{
    extern __shared__ __nv_bfloat16 sm[];
    __nv_bfloat16* sAh = sm;
    __nv_bfloat16* sAl = sm + 2 * A_BUF;
    __nv_bfloat16* sWh = sm + 4 * A_BUF;
    __nv_bfloat16* sWl = sm + 4 * A_BUF + 3 * W_BUF;
    const u32 bAh0 = (u32)__cvta_generic_to_shared(sAh);
    const u32 bAl0 = (u32)__cvta_generic_to_shared(sAl);
    const u32 bWh0 = (u32)__cvta_generic_to_shared(sWh);
    const u32 bWl0 = (u32)__cvta_generic_to_shared(sWl);

    const int t    = threadIdx.x;
    const int lane = t & 31;
    const int warp = t >> 5;
    const int wm   = warp >> 1;
    const int wn   = warp & 1;
    const int m0   = blockIdx.y * BM;
    const int n0   = blockIdx.x * BN;

    const int ar  = t >> 1;
    const int acb = (t & 1) * 16;
    const int wr = t >> 3;
    const int wc = t & 7;

    float av[16];

    auto load_a_regs = [&](int k0) {
        const float* p = A32 + (size_t)(m0 + ar) * K + k0 + acb;
        if (k0 + BKB <= K) {
#pragma unroll
            for (int i = 0; i < 4; i++) {
                float4 v = *(const float4*)(p + i * 4);
                av[4 * i]     = v.x;
                av[4 * i + 1] = v.y;
                av[4 * i + 2] = v.z;
                av[4 * i + 3] = v.w;
            }
        } else {
#pragma unroll
            for (int i = 0; i < 16; i++) {
                int c = k0 + acb + i;
                av[i] = (c < K) ? p[i] : 0.0f;
            }
        }
    };
    auto store_a_smem = [&](int buf) {
        __nv_bfloat16 hb[16], lb[16];
#pragma unroll
        for (int i = 0; i < 16; i++) {
            hb[i] = __float2bfloat16(av[i]);
            lb[i] = __float2bfloat16(av[i] - __bfloat162float(hb[i]));
        }
        int base = buf * A_BUF + ar * AST + acb;
#pragma unroll
        for (int hf = 0; hf < 2; hf++) {
            uint4 hv, lv;
            hv.x = pack_bf2(hb[8 * hf + 0], hb[8 * hf + 1]);
            hv.y = pack_bf2(hb[8 * hf + 2], hb[8 * hf + 3]);
            hv.z = pack_bf2(hb[8 * hf + 4], hb[8 * hf + 5]);
            hv.w = pack_bf2(hb[8 * hf + 6], hb[8 * hf + 7]);
            lv.x = pack_bf2(lb[8 * hf + 0], lb[8 * hf + 1]);
            lv.y = pack_bf2(lb[8 * hf + 2], lb[8 * hf + 3]);
            lv.z = pack_bf2(lb[8 * hf + 4], lb[8 * hf + 5]);
            lv.w = pack_bf2(lb[8 * hf + 6], lb[8 * hf + 7]);
            *(uint4*)(sAh + base + 8 * hf) = hv;
            *(uint4*)(sAl + base + 8 * hf) = lv;
        }
    };
    auto load_w = [&](int buf, int k0) {
#pragma unroll
        for (int i = 0; i < 2; i++) {
            int ch = wc + i * 8;
            size_t g = (size_t)(k0 + wr) * NP + n0 + ch * 8;
            u32 s = (u32)((buf * W_BUF + wr * WST + ch * 8) * 2);
            cp16(bWh0 + s, Wh + g);
            cp16(bWl0 + s, Wl + g);
        }
        cp_commit();
    };

    float acc[2][8][4];
#pragma unroll
    for (int mt = 0; mt < 2; mt++)
#pragma unroll
        for (int nt = 0; nt < 8; nt++)
#pragma unroll
            for (int e = 0; e < 4; e++) acc[mt][nt][e] = 0.0f;

    const int lrow = lane & 15;
    const int lcol = lane >> 4;
    const int ntiles = Kp / BKB;

    load_a_regs(0);
    store_a_smem(0);
    if (ntiles > 1) load_a_regs(BKB);
    load_w(0, 0);
    if (ntiles > 1) load_w(1, BKB);

    int wcur = 0;
    for (int tl = 0; tl < ntiles; ++tl) {
        const int cur = tl & 1;
        if (tl + 1 < ntiles) cp_wait<1>(); else cp_wait<0>();
        __syncthreads();

        int wnext = wcur + 2; if (wnext >= 3) wnext -= 3;
        if (tl + 2 < ntiles) load_w(wnext, (tl + 2) * BKB);

        if (tl + 1 < ntiles) store_a_smem(cur ^ 1);
        if (tl + 2 < ntiles) load_a_regs((tl + 2) * BKB);

        const u32 aHb = bAh0 + cur * A_BUF * 2;
        const u32 aLb = bAl0 + cur * A_BUF * 2;
        const u32 wHb = bWh0 + wcur * W_BUF * 2;
        const u32 wLb = bWl0 + wcur * W_BUF * 2;

#pragma unroll
        for (int kk = 0; kk < 2; kk++) {
            u32 aH[2][4], aL[2][4];
#pragma unroll
            for (int mt = 0; mt < 2; mt++) {
                u32 off = ((wm * 32 + mt * 16 + lrow) * AST + kk * 16 + lcol * 8) * 2;
                ldsm_x4(aH[mt], aHb + off);
                ldsm_x4(aL[mt], aLb + off);
            }
#pragma unroll
            for (int np2 = 0; np2 < 2; np2++) {
                u32 bH[2][4], bL[2][4];
#pragma unroll
                for (int q = 0; q < 2; q++) {
                    int nq = np2 * 2 + q;
                    u32 off = ((kk * 16 + lrow) * WST + wn * 64 + nq * 16 + lcol * 8) * 2;
                    ldsm_x4_t(bH[q], wHb + off);
                    ldsm_x4_t(bL[q], wLb + off);
                }
#pragma unroll
                for (int mt = 0; mt < 2; mt++)
#pragma unroll
                    for (int q = 0; q < 2; q++)
#pragma unroll
                        for (int j = 0; j < 2; j++)
                            mma_bf16(acc[mt][(np2 * 2 + q) * 2 + j], aH[mt], bH[q] + 2 * j);
#pragma unroll
                for (int mt = 0; mt < 2; mt++)
#pragma unroll
                    for (int q = 0; q < 2; q++)
#pragma unroll
                        for (int j = 0; j < 2; j++)
                            mma_bf16(acc[mt][(np2 * 2 + q) * 2 + j], aH[mt], bL[q] + 2 * j);
#pragma unroll
                for (int mt = 0; mt < 2; mt++)
#pragma unroll
                    for (int q = 0; q < 2; q++)
#pragma unroll
                        for (int j = 0; j < 2; j++)
                            mma_bf16(acc[mt][(np2 * 2 + q) * 2 + j], aL[mt], bH[q] + 2 * j);
            }
        }

        if (++wcur == 3) wcur = 0;
    }

    // epilogue: write bf16 hi/lo into [b, head, seq, HDP]
    const int seqlen = 1 << seqshift;
#pragma unroll
    for (int mt = 0; mt < 2; mt++) {
#pragma unroll
        for (int nt = 0; nt < 8; nt++) {
            int row = wm * 32 + mt * 16 + (lane >> 2);
            int col = wn * 64 + nt * 8 + (lane & 3) * 2;
#pragma unroll
            for (int e = 0; e < 4; e++) {
                int m = m0 + row + ((e >> 1) ? 8 : 0);
                int n = n0 + col + (e & 1);
                if (n >= PROJ_) continue;
                int head = n / HD;
                int c    = n - head * HD;
                int bi   = m >> seqshift;
                int si   = m & (seqlen - 1);
                float x = acc[mt][nt][e] + bias[n];
                __nv_bfloat16 h = __float2bfloat16(x);
                size_t o = ((size_t)(bi * HEADS + head) * seqlen + si) * HDP + c;
                DH[o] = h;
                DL[o] = __float2bfloat16(x - __bfloat162float(h));
            }
        }
    }
}

// ---------------- tensor-core attention: cp.async double-buffered K ---------
// smem layout (bytes):
//   [0, 18432)        QH (128 x 72 bf16)
//   [18432, 36864)    QL
//   buf b at 36864 + b*37376:  KH(18432) | KL(18432) | V(512 fp32 bytes)
#define ATT_ST 72
#define QH_OFF 0
#define QL_OFF 18432
#define KB_OFF 36864
#define KBUF   37376
#define KH_IN  0
#define KL_IN  18432
#define V_IN   36864
#define ATT_SMEM (KB_OFF + 2 * KBUF)     // 111616 B

__global__ __launch_bounds__(256, 2) void attn_tc(const float* __restrict__ value)
{
    extern __shared__ char smc[];
    const u32 sb = (u32)__cvta_generic_to_shared(smc);

    const int b  = blockIdx.z;
    const int h  = blockIdx.y;
    const int q0 = blockIdx.x * 128;
    const int t  = threadIdx.x;
    const int lane = t & 31;
    const int w    = t >> 5;

    const __nv_bfloat16* khg = g_kah + ((size_t)(b * HEADS + h) * LK_) * HDP;
    const __nv_bfloat16* klg = g_kal + ((size_t)(b * HEADS + h) * LK_) * HDP;
    const float* vg = value + (size_t)b * LK_;

    // K tile load via cp.async: 128 rows x 8 chunks per matrix; 4 chunks/thread
    const int kr = t >> 1;            // base row advance +... use idx mapping
    auto load_k = [&](int buf, int kt) {
        u32 kb = sb + KB_OFF + buf * KBUF;
#pragma unroll
        for (int i = 0; i < 4; i++) {
            int idx = t + i * 256;
            int r = idx >> 3, c = idx & 7;
            size_t g = (size_t)(kt + r) * HDP + c * 8;
            u32 d = (u32)((r * ATT_ST + c * 8) * 2);
            cp16(kb + KH_IN + d, khg + g);
            cp16(kb + KL_IN + d, klg + g);
        }
        if (t < 32)
            cp16(kb + V_IN + t * 16, vg + kt + t * 4);
        cp_commit();
    };

    // stage q tile (regular stores; covered by first loop barrier)
    {
        const __nv_bfloat16* qh = g_qah + ((size_t)(b * HEADS + h) * LQ_ + q0) * HDP;
        const __nv_bfloat16* ql = g_qal + ((size_t)(b * HEADS + h) * LQ_ + q0) * HDP;
#pragma unroll
        for (int i = 0; i < 4; i++) {
            int idx = t + i * 256;
            int r = idx >> 3, c = idx & 7;
            uint4 vh = *(const uint4*)(qh + (size_t)r * HDP + c * 8);
            uint4 vl = *(const uint4*)(ql + (size_t)r * HDP + c * 8);
            *(uint4*)(smc + QH_OFF + (r * ATT_ST + c * 8) * 2) = vh;
            *(uint4*)(smc + QL_OFF + (r * ATT_ST + c * 8) * 2) = vl;
        }
    }

    load_k(0, 0);   // prologue: K tile 0 in flight

    float accA[2] = {0.f, 0.f}, accL[2] = {0.f, 0.f};
    const float scale = 0.14142135623730951f;

    const int bg  = lane >> 3;
    const int bi8 = lane & 7;
    const int brow_off = ((bg & 2) ? 8 : 0) + bi8;
    const int bcol_off = (bg & 1) ? 8 : 0;

    const int NT = LK_ / 128;   // 8 tiles

    for (int tl = 0; tl < NT; ++tl) {
        const int cur = tl & 1;
        cp_wait<0>();            // K(tl) complete (single group in flight)
        __syncthreads();         // visible to all warps; prev reads done

        if (tl + 1 < NT) load_k(cur ^ 1, (tl + 1) * 128);  // overlaps compute

        const u32 kb  = sb + KB_OFF + cur * KBUF;
        const u32 kHb = kb + KH_IN;
        const u32 kLb = kb + KL_IN;
        const float* vsh = (const float*)(smc + KB_OFF + cur * KBUF + V_IN);

#pragma unroll
        for (int half = 0; half < 2; half++) {
            float S[8][4];
#pragma unroll
            for (int nt = 0; nt < 8; nt++)
#pragma unroll
                for (int e = 0; e < 4; e++) S[nt][e] = 0.0f;

#pragma unroll
            for (int ks = 0; ks < 4; ks++) {
                const int k0 = ks * 16;
                u32 aH[4], aL[4];
                {
                    u32 off = ((w * 16 + (lane & 15)) * ATT_ST + k0 + (lane >> 4) * 8) * 2;
                    ldsm_x4(aH, sb + QH_OFF + off);
                    ldsm_x4(aL, sb + QL_OFF + off);
                }
                u32 bH[4][4], bL[4][4];
#pragma unroll
                for (int ng2 = 0; ng2 < 4; ng2++) {
                    const int ng = half * 4 + ng2;
                    u32 off = ((ng * 16 + brow_off) * ATT_ST + k0 + bcol_off) * 2;
                    ldsm_x4(bH[ng2], kHb + off);
                    ldsm_x4(bL[ng2], kLb + off);
                }
#pragma unroll
                for (int ng2 = 0; ng2 < 4; ng2++)
#pragma unroll
                    for (int j = 0; j < 2; j++)
                        mma_bf16(S[2 * ng2 + j], aH, bH[ng2] + 2 * j);
#pragma unroll
                for (int ng2 = 0; ng2 < 4; ng2++)
#pragma unroll
                    for (int j = 0; j < 2; j++)
                        mma_bf16(S[2 * ng2 + j], aH, bL[ng2] + 2 * j);
#pragma unroll
                for (int ng2 = 0; ng2 < 4; ng2++)
#pragma unroll
                    for (int j = 0; j < 2; j++)
                        mma_bf16(S[2 * ng2 + j], aL, bH[ng2] + 2 * j);
            }

#pragma unroll
            for (int nt = 0; nt < 8; nt++) {
                int n = (half * 8 + nt) * 8 + (lane & 3) * 2;
                float v0 = vsh[n], v1 = vsh[n + 1];
                float e0 = __expf(S[nt][0] * scale);
                float e1 = __expf(S[nt][1] * scale);
                float e2 = __expf(S[nt][2] * scale);
                float e3 = __expf(S[nt][3] * scale);
                accA[0] += e0 * v0 + e1 * v1;
                accL[0] += e0 + e1;
                accA[1] += e2 * v0 + e3 * v1;
                accL[1] += e2 + e3;
            }
        }
    }

#pragma unroll
    for (int r = 0; r < 2; r++) {
#pragma unroll
        for (int o = 1; o <= 2; o <<= 1) {
            accA[r] += __shfl_xor_sync(0xffffffffu, accA[r], o);
            accL[r] += __shfl_xor_sync(0xffffffffu, accL[r], o);
        }
    }
    if ((lane & 3) == 0) {
        int row = q0 + w * 16 + (lane >> 2);
        g_attn[((size_t)b * LQ_ + row) * HEADS + h]     = accA[0] / accL[0];
        g_attn[((size_t)b * LQ_ + row + 8) * HEADS + h] = accA[1] / accL[1];
    }
}

// ---------------- tiny MLP ----------------
__global__ __launch_bounds__(256) void mlp_kernel(
    const float* __restrict__ W1, const float* __restrict__ b1,
    const float* __restrict__ W2, const float* __restrict__ b2,
    float* __restrict__ out)
{
    int idx = blockIdx.x * blockDim.x + threadIdx.x;
    if (idx >= B_ * LQ_) return;

    float o[HEADS];
#pragma unroll
    for (int i = 0; i < HEADS; i++) o[i] = g_attn[(size_t)idx * HEADS + i];

    float y = b2[0];
#pragma unroll
    for (int j = 0; j < 10; j++) {
        float hj = b1[j];
#pragma unroll
        for (int i = 0; i < HEADS; i++) hj += o[i] * W1[i * 10 + j];
        hj = fmaxf(hj, 0.0f);
        y += hj * W2[j];
    }
    out[idx] = fmaxf(y, 0.0f);
}

// ---------------------------------------------------------------------------
extern "C" void kernel_launch(void* const* d_in, const int* in_sizes, int n_in,
                              void* d_out, int out_size)
{
    const float* query = (const float*)d_in[0];
    const float* key   = (const float*)d_in[1];
    const float* value = (const float*)d_in[2];
    const float* Wq    = (const float*)d_in[3];
    const float* bq    = (const float*)d_in[4];
    const float* Wk    = (const float*)d_in[5];
    const float* bk    = (const float*)d_in[6];
    const float* W1    = (const float*)d_in[7];
    const float* b1    = (const float*)d_in[8];
    const float* W2    = (const float*)d_in[9];
    const float* b2    = (const float*)d_in[10];
    float* out = (float*)d_out;

    static cudaStream_t sQ = nullptr;
    static cudaEvent_t evFork = nullptr, evJoin = nullptr;
    if (sQ == nullptr) {
        cudaStreamCreateWithFlags(&sQ, cudaStreamNonBlocking);
        cudaEventCreateWithFlags(&evFork, cudaEventDisableTiming);
        cudaEventCreateWithFlags(&evJoin, cudaEventDisableTiming);
    }

    __nv_bfloat16 *wqh, *wql, *wkh, *wkl, *qah, *qal, *kah, *kal;
    cudaGetSymbolAddress((void**)&wqh, g_wqh);
    cudaGetSymbolAddress((void**)&wql, g_wql);
    cudaGetSymbolAddress((void**)&wkh, g_wkh);
    cudaGetSymbolAddress((void**)&wkl, g_wkl);
    cudaGetSymbolAddress((void**)&qah, g_qah);
    cudaGetSymbolAddress((void**)&qal, g_qal);
    cudaGetSymbolAddress((void**)&kah, g_kah);
    cudaGetSymbolAddress((void**)&kal, g_kal);

    cudaFuncSetAttribute(gemm_bf16x3_f,
                         cudaFuncAttributeMaxDynamicSharedMemorySize, GEMM_SMEM);
    cudaFuncSetAttribute(attn_tc,
                         cudaFuncAttributeMaxDynamicSharedMemorySize, ATT_SMEM);

    // ---- fork: q-chain on sQ, k-chain on the default stream (R14 topology) --
    cudaEventRecord(evFork, 0);
    cudaStreamWaitEvent(sQ, evFork, 0);

    split_bf16_v<<<KPQ, 64, 0, sQ>>>(Wq, wqh, wql, QIN, PROJ_, NP);
    {
        dim3 grid(NP / BN, (B_ * LQ_) / BM);
        gemm_bf16x3_f<<<grid, 256, GEMM_SMEM, sQ>>>(query, wqh, wql, bq,
                                                    qah, qal, QIN, KPQ, 11);
    }
    cudaEventRecord(evJoin, sQ);

    split_bf16_v<<<KPK, 64>>>(Wk, wkh, wkl, KIN, PROJ_, NP);
    {
        dim3 grid(NP / BN, (B_ * LK_) / BM);
        gemm_bf16x3_f<<<grid, 256, GEMM_SMEM>>>(key, wkh, wkl, bk,
                                                kah, kal, KIN, KPK, 10);
    }

    // ---- join ----
    cudaStreamWaitEvent(0, evJoin, 0);

    {
        dim3 grid(LQ_ / 128, HEADS, B_);
        attn_tc<<<grid, 256, ATT_SMEM>>>(value);
    }
    {
        int n = B_ * LQ_;
        mlp_kernel<<<(n + 255) / 256, 256>>>(W1, b1, W2, b2, out);
    }
}